// round 11
// baseline (speedup 1.0000x reference)
#include <cuda_runtime.h>
#include <math.h>

#define BATCH   8
#define NPTS    4096
#define SPLITS  16
#define SCAND   (NPTS / SPLITS)   // 256 candidates per split = one tile
#define TILE    256
#define GROUP   8                 // candidate group granularity for index recovery
#define BLOCK   64
#define Q       8                 // queries per thread
#define QPB     (BLOCK * Q)       // 512 queries per block
#define QCHUNKS_MAIN (NPTS / QPB) // 8
#define CBLOCK  128               // combine threads per block
#define QCHUNKS (NPTS / CBLOCK)   // 32 combine chunks per (dir,b)
#define NCOMBINE (QCHUNKS * BATCH * 2)  // 512 combine blocks

// Scratch (static device arrays; no allocation allowed)
__device__ unsigned long long g_pack[2 * BATCH * NPTS * SPLITS]; // (score|base) packed
__device__ float g_part[NCOMBINE];                               // per-chunk |diff|^5 sums
__device__ unsigned int g_ticket;                                // zero-init, self-resetting

// Order-preserving float -> uint32 map (monotone for all finite floats).
static __device__ __forceinline__ unsigned int fmap(float f) {
    unsigned int u = __float_as_uint(f);
    return (u & 0x80000000u) ? ~u : (u | 0x80000000u);
}
static __device__ __forceinline__ float funmap(unsigned int m) {
    return __uint_as_float((m & 0x80000000u) ? (m & 0x7FFFFFFFu) : ~m);
}

// Bit-exact rescore (identical fmaf sequence everywhere it is evaluated).
static __device__ __forceinline__ float score(float cx, float cy, float cz,
                                              float nqx, float nqy, float nqz) {
    float h = 0.5f * fmaf(cx, cx, fmaf(cy, cy, cz * cz));
    return fmaf(nqx, cx, fmaf(nqy, cy, fmaf(nqz, cz, h)));
}

// Main: each thread owns 8 queries, scans this block's 256-candidate split.
// Objective: h - q.c, h = 0.5|c|^2 (|q|^2 dropped, argmin-invariant).
// Writes one packed u64 per (query, split): [mapped score | 8-group base].
__global__ void __launch_bounds__(BLOCK) chamfer_main(
    const float* __restrict__ x, const float* __restrict__ y)
{
    const int qchunk = blockIdx.x >> 4;    // 0..7
    const int split  = blockIdx.x & 15;    // 0..15
    const int b   = blockIdx.y;
    const int dir = blockIdx.z;
    const float* q  = (dir == 0) ? x : y;
    const float* db = (dir == 0) ? y : x;
    const float* qb  = q  + (size_t)b * NPTS * 3;
    const float* dbb = db + (size_t)b * NPTS * 3;

    float nqx[Q], nqy[Q], nqz[Q];
    #pragma unroll
    for (int k = 0; k < Q; k++) {
        const int qi = qchunk * QPB + threadIdx.x + k * BLOCK;
        nqx[k] = -qb[qi*3+0];
        nqy[k] = -qb[qi*3+1];
        nqz[k] = -qb[qi*3+2];
    }

    __shared__ float4 sh[TILE];

    const int cbeg = split * SCAND;
    #pragma unroll
    for (int k = 0; k < TILE / BLOCK; k++) {
        const int cl = threadIdx.x + k * BLOCK;
        const int c  = cbeg + cl;
        float cx = dbb[c*3+0], cy = dbb[c*3+1], cz = dbb[c*3+2];
        sh[cl] = make_float4(cx, cy, cz, 0.5f * fmaf(cx, cx, fmaf(cy, cy, cz * cz)));
    }
    __syncthreads();

    float best[Q];
    int   base[Q];
    #pragma unroll
    for (int k = 0; k < Q; k++) { best[k] = 3.4e38f; base[k] = cbeg; }

    for (int g = 0; g < TILE / GROUP; g++) {   // 32 groups of 8
        float prev[Q];
        #pragma unroll
        for (int k = 0; k < Q; k++) prev[k] = best[k];
        #pragma unroll
        for (int j = 0; j < GROUP; j++) {
            float4 c = sh[g * GROUP + j];   // broadcast LDS.128, feeds 8 chains
            #pragma unroll
            for (int k = 0; k < Q; k++)
                best[k] = fminf(best[k],
                    fmaf(nqx[k], c.x, fmaf(nqy[k], c.y, fmaf(nqz[k], c.z, c.w))));
        }
        const int gb = cbeg + g * GROUP;
        #pragma unroll
        for (int k = 0; k < Q; k++)
            if (best[k] < prev[k]) base[k] = gb;   // strict <: earliest group wins
    }

    const int qs = (dir * BATCH + b) * NPTS;
    #pragma unroll
    for (int k = 0; k < Q; k++) {
        const int qi = qchunk * QPB + threadIdx.x + k * BLOCK;
        g_pack[(qs + qi) * SPLITS + split] =
            ((unsigned long long)fmap(best[k]) << 32) | (unsigned int)base[k];
    }
}

// Combine: u64 min over 16 splits (LDG.128 x8; equal score bits -> smaller
// base = earlier candidate wins), then warp-cooperative rescan of the winning
// 8-group: round r covers queries 4r..4r+3 of the warp; lane j scores query
// (4r + j/8)'s candidate base+(j%8); one ballot resolves 4 queries. ffs of the
// 8-bit sub-mask = first exact match = first min. Then NN gather, per-chunk
// reduction; LAST block (ticket) folds the final result.
__global__ void __launch_bounds__(CBLOCK) combine_kernel(
    const float* __restrict__ x, const float* __restrict__ y,
    float* __restrict__ out)
{
    const int chunk = blockIdx.x;
    const int b   = blockIdx.y;
    const int dir = blockIdx.z;
    const int qi  = chunk * CBLOCK + threadIdx.x;
    const int lane = threadIdx.x & 31;
    const int wbase = threadIdx.x & ~31;
    const float* q  = (dir == 0) ? x : y;
    const float* db = (dir == 0) ? y : x;
    const float* qb  = q  + (size_t)b * NPTS * 3;
    const float* dbb = db + (size_t)b * NPTS * 3;

    // Split min: 16 u64 = 128 B contiguous per thread -> 8x LDG.128.
    const int slot = ((dir * BATCH + b) * NPTS + qi) * SPLITS;
    const ulonglong2* pp = reinterpret_cast<const ulonglong2*>(&g_pack[slot]);
    unsigned long long w = 0xFFFFFFFFFFFFFFFFull;
    #pragma unroll
    for (int s = 0; s < SPLITS / 2; s++) {
        ulonglong2 v = pp[s];
        unsigned long long m = (v.x < v.y) ? v.x : v.y;
        w = (m < w) ? m : w;
    }
    const float bb  = funmap((unsigned int)(w >> 32));
    const int  base = (int)(w & 0xFFFFFFFFu);

    const float qx = qb[qi*3+0], qy = qb[qi*3+1], qz = qb[qi*3+2];

    // Park per-query records in shared for intra-warp broadcast.
    __shared__ float4 sQ[CBLOCK];   // (nqx, nqy, nqz, bb)
    __shared__ int    sB[CBLOCK];   // 8-group base
    sQ[threadIdx.x] = make_float4(-qx, -qy, -qz, bb);
    sB[threadIdx.x] = base;
    __syncwarp();

    const int sub = lane >> 3;   // which of 4 queries this lane serves (0..3)
    const int off = lane & 7;    // candidate offset within the 8-group
    const int myr = lane >> 2;   // round in which THIS lane receives its answer
    const int mys = lane & 3;    // its slot within that round
    int bi = base;
    #pragma unroll
    for (int r = 0; r < 8; r++) {
        const int qslot = wbase + r * 4 + sub;
        const float4 rq = sQ[qslot];    // LDS.128 (4-way broadcast)
        const int    bw = sB[qslot];    // LDS
        const int c = bw + off;
        float d = score(dbb[c*3+0], dbb[c*3+1], dbb[c*3+2], rq.x, rq.y, rq.z);
        unsigned int mask = __ballot_sync(0xFFFFFFFFu, d == rq.w);
        if (myr == r) {
            unsigned int sub8 = (mask >> (8 * mys)) & 0xFFu;  // nonzero guaranteed
            bi = base + (__ffs(sub8) - 1);
        }
    }

    float nx = dbb[bi*3+0], ny = dbb[bi*3+1], nz = dbb[bi*3+2];
    float ax = fabsf(qx - nx), ay = fabsf(qy - ny), az = fabsf(qz - nz);
    float ax2 = ax * ax, ay2 = ay * ay, az2 = az * az;
    float v = ax2 * ax2 * ax + ay2 * ay2 * ay + az2 * az2 * az;

    __shared__ float red[CBLOCK];
    red[threadIdx.x] = v;
    __syncthreads();
    #pragma unroll
    for (int stride = CBLOCK / 2; stride >= 32; stride >>= 1) {
        if (threadIdx.x < stride) red[threadIdx.x] += red[threadIdx.x + stride];
        __syncthreads();
    }
    __shared__ bool s_last;
    if (threadIdx.x < 32) {
        float r = red[threadIdx.x];
        #pragma unroll
        for (int off2 = 16; off2 > 0; off2 >>= 1)
            r += __shfl_down_sync(0xFFFFFFFF, r, off2);
        if (threadIdx.x == 0) {
            g_part[(dir * BATCH + b) * QCHUNKS + chunk] = r;
            __threadfence();
            unsigned int t = atomicAdd(&g_ticket, 1u);
            s_last = (t == NCOMBINE - 1);
        }
    }
    __syncthreads();

    if (s_last) {
        // Final reduction, fused into the last-arriving block.
        __shared__ float sp[NCOMBINE];
        __shared__ float roots[2 * BATCH];
        #pragma unroll
        for (int k = 0; k < NCOMBINE / CBLOCK; k++)
            sp[threadIdx.x + k * CBLOCK] = g_part[threadIdx.x + k * CBLOCK];
        __syncthreads();
        if (threadIdx.x < 2 * BATCH) {
            float s = 0.0f;
            #pragma unroll
            for (int c = 0; c < QCHUNKS; c++) s += sp[threadIdx.x * QCHUNKS + c];
            roots[threadIdx.x] = powf(s, 0.2f);
        }
        __syncthreads();
        if (threadIdx.x == 0) {
            float acc = 0.0f;
            #pragma unroll
            for (int i = 0; i < 2 * BATCH; i++) acc += roots[i];
            out[0] = acc / (float)BATCH;
            g_ticket = 0;   // reset for next graph replay (deterministic)
        }
    }
}

extern "C" void kernel_launch(void* const* d_in, const int* in_sizes, int n_in,
                              void* d_out, int out_size)
{
    const float* x = (const float*)d_in[0];
    const float* y = (const float*)d_in[1];
    float* out = (float*)d_out;

    dim3 grid(QCHUNKS_MAIN * SPLITS, BATCH, 2);   // 128 x 8 x 2 = 2048 blocks
    chamfer_main<<<grid, BLOCK>>>(x, y);

    dim3 cgrid(QCHUNKS, BATCH, 2);                // 32 x 8 x 2 = 512 blocks
    combine_kernel<<<cgrid, CBLOCK>>>(x, y, out);
}

// round 12
// speedup vs baseline: 1.0747x; 1.0747x over previous
#include <cuda_runtime.h>
#include <math.h>

#define BATCH   8
#define NPTS    4096
#define SPLITS  16
#define SCAND   (NPTS / SPLITS)   // 256 candidates per split = one tile
#define TILE    256
#define BLOCK   64
#define Q       8                 // queries per thread
#define QPB     (BLOCK * Q)       // 512 queries per block
#define QCHUNKS_MAIN (NPTS / QPB) // 8
#define CBLOCK  64                // combine threads per block
#define QCHUNKS (NPTS / CBLOCK)   // 64 combine chunks per (dir,b)
#define NCOMBINE (QCHUNKS * BATCH * 2)  // 1024 combine blocks
#define PAD     65                // row stride (65 mod 32 = 1 -> conflict-free)

// Scratch (static device arrays; no allocation allowed)
__device__ unsigned long long g_pack[2 * BATCH * NPTS * SPLITS]; // (score|base) packed
__device__ float g_part[NCOMBINE];                               // per-chunk |diff|^5 sums
__device__ unsigned int g_ticket;                                // zero-init, self-resetting

// Order-preserving float -> uint32 map (monotone for all finite floats).
static __device__ __forceinline__ unsigned int fmap(float f) {
    unsigned int u = __float_as_uint(f);
    return (u & 0x80000000u) ? ~u : (u | 0x80000000u);
}
static __device__ __forceinline__ float funmap(unsigned int m) {
    return __uint_as_float((m & 0x80000000u) ? (m & 0x7FFFFFFFu) : ~m);
}

// Main: each thread owns 8 queries, scans this block's 256-candidate split.
// Objective: h - q.c, h = 0.5|c|^2 (|q|^2 dropped, argmin-invariant).
// Writes one packed u64 per (query, split): [mapped score | 32-group base].
// EXACT copy of the round-10 kernel (proven at the FFMA-pipe floor).
__global__ void __launch_bounds__(BLOCK) chamfer_main(
    const float* __restrict__ x, const float* __restrict__ y)
{
    const int qchunk = blockIdx.x >> 4;    // 0..7
    const int split  = blockIdx.x & 15;    // 0..15
    const int b   = blockIdx.y;
    const int dir = blockIdx.z;
    const float* q  = (dir == 0) ? x : y;
    const float* db = (dir == 0) ? y : x;
    const float* qb  = q  + (size_t)b * NPTS * 3;
    const float* dbb = db + (size_t)b * NPTS * 3;

    float nqx[Q], nqy[Q], nqz[Q];
    #pragma unroll
    for (int k = 0; k < Q; k++) {
        const int qi = qchunk * QPB + threadIdx.x + k * BLOCK;
        nqx[k] = -qb[qi*3+0];
        nqy[k] = -qb[qi*3+1];
        nqz[k] = -qb[qi*3+2];
    }

    __shared__ float4 sh[TILE];

    const int cbeg = split * SCAND;
    #pragma unroll
    for (int k = 0; k < TILE / BLOCK; k++) {
        const int cl = threadIdx.x + k * BLOCK;
        const int c  = cbeg + cl;
        float cx = dbb[c*3+0], cy = dbb[c*3+1], cz = dbb[c*3+2];
        sh[cl] = make_float4(cx, cy, cz, 0.5f * fmaf(cx, cx, fmaf(cy, cy, cz * cz)));
    }
    __syncthreads();

    float best[Q];
    int   base[Q];
    #pragma unroll
    for (int k = 0; k < Q; k++) { best[k] = 3.4e38f; base[k] = cbeg; }

    #pragma unroll
    for (int g = 0; g < TILE / 32; g++) {
        float prev[Q];
        #pragma unroll
        for (int k = 0; k < Q; k++) prev[k] = best[k];
        #pragma unroll 8
        for (int j = 0; j < 32; j++) {
            float4 c = sh[g * 32 + j];   // broadcast LDS.128, feeds 8 chains
            #pragma unroll
            for (int k = 0; k < Q; k++)
                best[k] = fminf(best[k],
                    fmaf(nqx[k], c.x, fmaf(nqy[k], c.y, fmaf(nqz[k], c.z, c.w))));
        }
        const int gb = cbeg + g * 32;
        #pragma unroll
        for (int k = 0; k < Q; k++)
            if (best[k] < prev[k]) base[k] = gb;   // strict <: earliest group wins
    }

    const int qs = (dir * BATCH + b) * NPTS;
    #pragma unroll
    for (int k = 0; k < Q; k++) {
        const int qi = qchunk * QPB + threadIdx.x + k * BLOCK;
        g_pack[(qs + qi) * SPLITS + split] =
            ((unsigned long long)fmap(best[k]) << 32) | (unsigned int)base[k];
    }
}

// Combine: u64 min over 16 splits (8x LDG.128; equal score bits -> smaller
// base = earlier candidate wins). Then STAGE-AND-SCAN index recovery:
//   stage: warp w, iteration g -> lane j loads candidate (base of thread
//          w*32+g) + j (coalesced 384B/group, 96 independent LDGs/warp),
//          stores SoA rows (stride PAD=65, conflict-free both phases).
//   scan:  each thread rescans ITS group from shared, branchless descending-j
//          (last writer = smallest j = first min; bit-exact fmaf chain).
// NN coords come straight from the staged shared copy. Per-chunk reduction;
// LAST block (ticket) folds the final result into out[0].
__global__ void __launch_bounds__(CBLOCK) combine_kernel(
    const float* __restrict__ x, const float* __restrict__ y,
    float* __restrict__ out)
{
    const int chunk = blockIdx.x;
    const int b   = blockIdx.y;
    const int dir = blockIdx.z;
    const int qi  = chunk * CBLOCK + threadIdx.x;
    const int lane = threadIdx.x & 31;
    const int wb   = threadIdx.x & ~31;
    const float* q  = (dir == 0) ? x : y;
    const float* db = (dir == 0) ? y : x;
    const float* qb  = q  + (size_t)b * NPTS * 3;
    const float* dbb = db + (size_t)b * NPTS * 3;

    // Split min: 16 u64 = 128 B contiguous per thread -> 8x LDG.128.
    const int slot = ((dir * BATCH + b) * NPTS + qi) * SPLITS;
    const ulonglong2* pp = reinterpret_cast<const ulonglong2*>(&g_pack[slot]);
    unsigned long long w = 0xFFFFFFFFFFFFFFFFull;
    #pragma unroll
    for (int s = 0; s < SPLITS / 2; s++) {
        ulonglong2 v = pp[s];
        unsigned long long m = (v.x < v.y) ? v.x : v.y;
        w = (m < w) ? m : w;
    }
    const float bb  = funmap((unsigned int)(w >> 32));
    const int  base = (int)(w & 0xFFFFFFFFu);

    const float qx = qb[qi*3+0], qy = qb[qi*3+1], qz = qb[qi*3+2];
    const float nqxv = -qx, nqyv = -qy, nqzv = -qz;

    __shared__ int   sB[CBLOCK];
    __shared__ float shX[32 * PAD], shY[32 * PAD], shZ[32 * PAD];
    sB[threadIdx.x] = base;
    __syncwarp();

    // Stage: iteration g targets thread (wb+g)'s group; lane j fetches its
    // candidate j. All 96 LDGs independent -> full MLP, no round-trips.
    #pragma unroll 4
    for (int g = 0; g < 32; g++) {
        const int t  = wb + g;
        const int c  = sB[t] + lane;         // LDS broadcast
        shX[lane * PAD + t] = dbb[c*3+0];    // lane stride PAD=65 -> no conflicts
        shY[lane * PAD + t] = dbb[c*3+1];
        shZ[lane * PAD + t] = dbb[c*3+2];
    }
    __syncwarp();

    // Scan own group, branchless, descending j (first-min semantics).
    int firstj = 0;
    float nx = 0.f, ny = 0.f, nz = 0.f;
    #pragma unroll 8
    for (int j = 31; j >= 0; j--) {
        float cx = shX[j * PAD + threadIdx.x];   // lane stride 1 -> no conflicts
        float cy = shY[j * PAD + threadIdx.x];
        float cz = shZ[j * PAD + threadIdx.x];
        float h  = 0.5f * fmaf(cx, cx, fmaf(cy, cy, cz * cz));
        float d  = fmaf(nqxv, cx, fmaf(nqyv, cy, fmaf(nqzv, cz, h)));
        bool hit = (d == bb);                    // bit-exact -> guaranteed >=1 hit
        firstj = hit ? j : firstj;
        nx = hit ? cx : nx;  ny = hit ? cy : ny;  nz = hit ? cz : nz;
    }
    (void)firstj;

    float ax = fabsf(qx - nx), ay = fabsf(qy - ny), az = fabsf(qz - nz);
    float ax2 = ax * ax, ay2 = ay * ay, az2 = az * az;
    float v = ax2 * ax2 * ax + ay2 * ay2 * ay + az2 * az2 * az;

    __shared__ float red[CBLOCK];
    red[threadIdx.x] = v;
    __syncthreads();
    if (threadIdx.x < 32) {
        float r = red[threadIdx.x] + red[threadIdx.x + 32];
        #pragma unroll
        for (int off = 16; off > 0; off >>= 1)
            r += __shfl_down_sync(0xFFFFFFFF, r, off);
        __shared__ bool s_last;
        if (threadIdx.x == 0) {
            g_part[(dir * BATCH + b) * QCHUNKS + chunk] = r;
            __threadfence();
            unsigned int t = atomicAdd(&g_ticket, 1u);
            s_last = (t == NCOMBINE - 1);
        }
        __syncwarp();
        if (s_last) {
            // Final fold in the last-arriving block's first warp.
            float acc = 0.0f;
            // Each lane sums one (dir,b) strip when lane < 16, takes root.
            if (threadIdx.x < 2 * BATCH) {
                float s = 0.0f;
                for (int c = 0; c < QCHUNKS; c++)
                    s += g_part[threadIdx.x * QCHUNKS + c];
                acc = powf(s, 0.2f);
            }
            #pragma unroll
            for (int off = 16; off > 0; off >>= 1)
                acc += __shfl_down_sync(0xFFFFFFFF, acc, off);
            if (threadIdx.x == 0) {
                out[0] = acc / (float)BATCH;
                g_ticket = 0;   // reset for next graph replay (deterministic)
            }
        }
    }
}

extern "C" void kernel_launch(void* const* d_in, const int* in_sizes, int n_in,
                              void* d_out, int out_size)
{
    const float* x = (const float*)d_in[0];
    const float* y = (const float*)d_in[1];
    float* out = (float*)d_out;

    dim3 grid(QCHUNKS_MAIN * SPLITS, BATCH, 2);   // 128 x 8 x 2 = 2048 blocks
    chamfer_main<<<grid, BLOCK>>>(x, y);

    dim3 cgrid(QCHUNKS, BATCH, 2);                // 64 x 8 x 2 = 1024 blocks
    combine_kernel<<<cgrid, CBLOCK>>>(x, y, out);
}